// round 15
// baseline (speedup 1.0000x reference)
#include <cuda_runtime.h>
#include <cuda_fp16.h>
#include <cstdint>

#define M_TOTAL (64 * 2048)   // 131072 rows
#define KDIM 128
#define HID 256
#define BM 64                 // M per CTA
#define NJ 32                 // j per CTA (N = 3*32 = 96)
#define NJGRP 8               // 8 j-groups cover HID=256
#define NTHREADS 128
#define MTILES (M_TOTAL / BM) // 2048

// SMEM layout (bytes): bias | B frags | A tile  (40.5KB -> 5 CTA/SM)
#define BIAS_OFF 0
#define B_OFF 512
#define B_BYTES (4 * 3 * 8 * 32 * 8)     // jf*gate*ks*lane*8B = 24576 per jgrp
#define A_OFF (B_OFF + B_BYTES)          // 25088
#define A_BYTES (BM * KDIM * 2)          // 16384 fp16 swizzled
#define SMEM_BYTES (A_OFF + A_BYTES)     // 41472

// ---------------- device scratch ----------------
__device__ __half g_Wp[NJGRP * (B_BYTES / 2)];  // fp16 B fragments (j-permuted)
__device__ float g_bias[NJGRP * 96];            // [jgrp][gate 3][32]

// Pack two f32 into f16x2 (lo = a, hi = b).
__device__ __forceinline__ uint32_t pack_f16x2(float a, float b) {
    uint32_t r;
    asm("cvt.rn.f16x2.f32 %0, %1, %2;" : "=r"(r) : "f"(b), "f"(a));
    return r;
}

// W fragment packing + bias. B columns PERMUTED so each thread's 4
// accumulator columns are 4 consecutive logical j (proven in round 14):
//   j_local = (jf>>1)*16 + 4*(n>>1) + 2*(jf&1) + (n&1)
__global__ void prep_kernel(const float* __restrict__ W_ih,
                            const float* __restrict__ b_ih,
                            const float* __restrict__ b_hh) {
    int g = blockIdx.x * blockDim.x + threadIdx.x;
    if (g < NJGRP * 96) {
        int jgrp = g / 96, r = g % 96;
        int gate = r / 32, jl = r % 32;
        int src = (gate == 0 ? 0 : (gate == 1 ? 512 : 768)) + jgrp * 32 + jl;
        g_bias[g] = b_ih[src] + b_hh[src];
    }
    if (g >= NJGRP * 12288) return;
    // fp16 B-frag coords: [jgrp 8][jf 4][gate 3][ks 8][lane 32][4 halves]
    int jgrp = g / 12288;         int r1 = g % 12288;
    int jf  = r1 / 3072;          int r2 = r1 % 3072;
    int gate = r2 / 1024;         int r3 = r2 % 1024;
    int ks  = r3 / 128;           int r4 = r3 % 128;
    int lane = r4 >> 2;           int rr = r4 & 3;
    int pair = rr >> 1;           int half = rr & 1;
    int gid = lane >> 2, tig = lane & 3;   // gid = fragment n
    int k = ks * 16 + pair * 8 + 2 * tig + half;
    int j_global = jgrp * 32 + (jf >> 1) * 16 + ((gid >> 1) << 2)
                 + (jf & 1) * 2 + (gid & 1);
    int src_row = (gate == 0 ? 0 : (gate == 1 ? 512 : 768)) + j_global;
    g_Wp[g] = __float2half_rn(W_ih[src_row * KDIM + k]);
}

// ---------------- helpers ----------------
__device__ __forceinline__ uint32_t smem_u32(const void* p) {
    uint32_t a;
    asm("{ .reg .u64 t; cvta.to.shared.u64 t, %1; cvt.u32.u64 %0, t; }" : "=r"(a) : "l"(p));
    return a;
}
__device__ __forceinline__ void cp_async16(uint32_t dst, const void* src) {
    asm volatile("cp.async.cg.shared.global [%0], [%1], 16;" :: "r"(dst), "l"(src));
}
__device__ __forceinline__ void cp_async_wait_all() {
    asm volatile("cp.async.commit_group;\ncp.async.wait_group 0;" ::: "memory");
}
__device__ __forceinline__ void mma_f16(float (&dacc)[4], const uint32_t (&a)[4],
                                        const uint32_t (&b)[2]) {
    asm volatile(
        "mma.sync.aligned.m16n8k16.row.col.f32.f16.f16.f32 "
        "{%0,%1,%2,%3}, {%4,%5,%6,%7}, {%8,%9}, {%0,%1,%2,%3};"
        : "+f"(dacc[0]), "+f"(dacc[1]), "+f"(dacc[2]), "+f"(dacc[3])
        : "r"(a[0]), "r"(a[1]), "r"(a[2]), "r"(a[3]), "r"(b[0]), "r"(b[1]));
}
__device__ __forceinline__ void ldsm_x4(uint32_t (&a)[4], uint32_t addr) {
    asm volatile("ldmatrix.sync.aligned.m8n8.x4.shared.b16 {%0,%1,%2,%3}, [%4];"
                 : "=r"(a[0]), "=r"(a[1]), "=r"(a[2]), "=r"(a[3]) : "r"(addr));
}
__device__ __forceinline__ float tanh_ap(float x) {
    float y;
    asm("tanh.approx.f32 %0, %1;" : "=f"(y) : "f"(x));
    return y;
}
__device__ __forceinline__ float sig_ap(float x) {
    return fmaf(0.5f, tanh_ap(0.5f * x), 0.5f);
}
__device__ __forceinline__ void stg_cs_f4(float* p, float4 v) {
    asm volatile("st.global.cs.v4.f32 [%0], {%1, %2, %3, %4};"
                 :: "l"(p), "f"(v.x), "f"(v.y), "f"(v.z), "f"(v.w));
}

__global__ __launch_bounds__(NTHREADS, 5)
void lstm_mma_kernel(const float* __restrict__ x, float* __restrict__ out) {
    extern __shared__ char smc[];
    float* bias_s = (float*)(smc + BIAS_OFF);
    char* Bs = smc + B_OFF;
    const uint32_t sb = smem_u32(smc);

    const int tid = threadIdx.x;
    const int lane = tid & 31;
    const int wid = tid >> 5;      // 0..3
    const int gid = lane >> 2;
    const int tig = lane & 3;
    const int wm = wid & 1;        // 2 m-warps * 32 rows
    const int wj = wid >> 1;       // 2 j-warps * (2 jf * 3 gates = 48 cols)
    // m-major: the 8 jgrp-siblings of one m-tile are adjacent -> share x via L2.
    const int jgrp = blockIdx.x & 7;
    const int bm = (blockIdx.x >> 3) * BM;

    // B fragments via cp.async (B totals 192KB -> L2-resident)
    {
        const char* Bg = (const char*)g_Wp + (size_t)jgrp * B_BYTES;
#pragma unroll
        for (int i = 0; i < 12; ++i) {
            int c = i * NTHREADS + tid;
            cp_async16(sb + B_OFF + c * 16, Bg + c * 16);
        }
    }
    if (tid < 96) bias_s[tid] = g_bias[jgrp * 96 + tid];

    // A tile: LDG f32 -> convert fp16 -> swizzled STS (fused conversion).
    {
        const float4* src = (const float4*)(x + (size_t)bm * KDIM);
#pragma unroll
        for (int i = 0; i < 8; ++i) {
            int idx = i * NTHREADS + tid;     // 16B-chunk index 0..1023
            int row = idx >> 4, q = idx & 15;
            float4 v0 = src[(row << 5) + q * 2];
            float4 v1 = src[(row << 5) + q * 2 + 1];
            uint4 hv;
            hv.x = pack_f16x2(v0.x, v0.y);
            hv.y = pack_f16x2(v0.z, v0.w);
            hv.z = pack_f16x2(v1.x, v1.y);
            hv.w = pack_f16x2(v1.z, v1.w);
            *(uint4*)(smc + A_OFF + row * 256 + ((q ^ (row & 7)) << 4)) = hv;
        }
    }
    cp_async_wait_all();
    __syncthreads();

    const int rb0 = wm * 32;
    const int lrow0 = rb0 + (lane & 7) + ((lane >> 3) & 1) * 8;
    const int lhi = lane >> 4;
    const uint32_t Au = sb + A_OFF;
    const char* Bw = Bs + (size_t)(wj * 2) * 3 * 8 * 256 + lane * 8;

    float acc[2][2][3][4];
#pragma unroll
    for (int mf = 0; mf < 2; ++mf)
#pragma unroll
        for (int jf = 0; jf < 2; ++jf)
#pragma unroll
            for (int g = 0; g < 3; ++g)
#pragma unroll
                for (int q = 0; q < 4; ++q) acc[mf][jf][g][q] = 0.0f;

    // Software pipeline: stage ks+1 loads while issuing ks MMAs.
    uint32_t a_cur[2][4], a_nxt[2][4];
    uint2 b_cur[2][3], b_nxt[2][3];
#pragma unroll
    for (int mf = 0; mf < 2; ++mf) {
        const int row = lrow0 + mf * 16;
        ldsm_x4(a_cur[mf], Au + row * 256 + ((lhi ^ (row & 7)) << 4));
    }
#pragma unroll
    for (int jf = 0; jf < 2; ++jf)
#pragma unroll
        for (int g = 0; g < 3; ++g)
            b_cur[jf][g] = *(const uint2*)(Bw + ((jf * 3 + g) * 8) * 256);

#pragma unroll
    for (int ks = 0; ks < 8; ++ks) {
        if (ks < 7) {
#pragma unroll
            for (int mf = 0; mf < 2; ++mf) {
                const int row = lrow0 + mf * 16;
                ldsm_x4(a_nxt[mf],
                        Au + row * 256 + ((((ks + 1) * 2 + lhi) ^ (row & 7)) << 4));
            }
#pragma unroll
            for (int jf = 0; jf < 2; ++jf)
#pragma unroll
                for (int g = 0; g < 3; ++g)
                    b_nxt[jf][g] = *(const uint2*)
                        (Bw + (((jf * 3 + g) * 8) + ks + 1) * 256);
        }
#pragma unroll
        for (int jf = 0; jf < 2; ++jf)
#pragma unroll
            for (int g = 0; g < 3; ++g) {
                uint32_t b[2] = { b_cur[jf][g].x, b_cur[jf][g].y };
#pragma unroll
                for (int mf = 0; mf < 2; ++mf)
                    mma_f16(acc[mf][jf][g], a_cur[mf], b);
            }
#pragma unroll
        for (int mf = 0; mf < 2; ++mf)
#pragma unroll
            for (int q = 0; q < 4; ++q) a_cur[mf][q] = a_nxt[mf][q];
#pragma unroll
        for (int jf = 0; jf < 2; ++jf)
#pragma unroll
            for (int g = 0; g < 3; ++g) b_cur[jf][g] = b_nxt[jf][g];
    }

    // Epilogue: B permutation makes this thread's 4 accumulator columns
    // logical j = jl4..jl4+3 -> float4 coalesced stores.
    const int jl4 = wj * 16 + 4 * tig;
    const float4 bi = *(const float4*)(bias_s + jl4);
    const float4 bg = *(const float4*)(bias_s + 32 + jl4);
    const float4 bo = *(const float4*)(bias_s + 64 + jl4);
    const int jcol = jgrp * 32 + jl4;
#pragma unroll
    for (int mf = 0; mf < 2; ++mf) {
        const int m0 = bm + rb0 + mf * 16 + gid;
#pragma unroll
        for (int rr = 0; rr < 2; ++rr) {
            float4 hv, cv;
#pragma unroll
            for (int t = 0; t < 4; ++t) {
                const int jfl = t >> 1, co = t & 1;
                float iv = sig_ap(acc[mf][jfl][0][rr * 2 + co] + ((const float*)&bi)[t]);
                float gv = tanh_ap(acc[mf][jfl][1][rr * 2 + co] + ((const float*)&bg)[t]);
                float ov = sig_ap(acc[mf][jfl][2][rr * 2 + co] + ((const float*)&bo)[t]);
                float cc = iv * gv;
                float hh = ov * tanh_ap(cc);
                ((float*)&hv)[t] = hh;
                ((float*)&cv)[t] = cc;
            }
            size_t off = (size_t)(m0 + rr * 8) * HID + jcol;
            stg_cs_f4(out + off, hv);
            stg_cs_f4(out + (size_t)M_TOTAL * HID + off, cv);
        }
    }
}

extern "C" void kernel_launch(void* const* d_in, const int* in_sizes, int n_in,
                              void* d_out, int out_size) {
    const float* x    = (const float*)d_in[0];
    const float* W_ih = (const float*)d_in[1];
    // d_in[2] = W_hh unused (h_prev == 0 in reference)
    const float* b_ih = (const float*)d_in[3];
    const float* b_hh = (const float*)d_in[4];
    float* out = (float*)d_out;

    cudaFuncSetAttribute(lstm_mma_kernel,
                         cudaFuncAttributeMaxDynamicSharedMemorySize, SMEM_BYTES);

    prep_kernel<<<(NJGRP * 12288 + 511) / 512, 512>>>(W_ih, b_ih, b_hh);
    lstm_mma_kernel<<<NJGRP * MTILES, NTHREADS, SMEM_BYTES>>>(x, out);
}

// round 16
// speedup vs baseline: 1.2903x; 1.2903x over previous
#include <cuda_runtime.h>
#include <cuda_fp16.h>
#include <cstdint>

#define M_TOTAL (64 * 2048)   // 131072 rows
#define KDIM 128
#define HID 256
#define NPACK 768             // i,g,o gates only (f-gate dead: c_prev == 0)
#define BM 128
#define NGRP 4
#define NTHREADS 256
#define MTILES (M_TOTAL / BM) // 1024

// SMEM layout (bytes): bias | B frags | A tile
#define BIAS_OFF 0
#define B_OFF 1024
#define B_BYTES (8 * 3 * 8 * 32 * 8)     // 49152 per group
#define A_OFF (B_OFF + B_BYTES)          // 50176
#define A_BYTES (BM * KDIM * 2)          // 32768 fp16 swizzled
#define SMEM_BYTES (A_OFF + A_BYTES)     // 82944

// ---------------- device scratch ----------------
__device__ __half g_Wp[NGRP * (B_BYTES / 2)];   // fp16 B fragments (j-permuted)
__device__ float g_bias[NGRP * 192];            // [grp][gate 3][64]
__device__ __half g_xh[M_TOTAL * KDIM];         // x fp16, ldmatrix-swizzled rows

// Pack two f32 into f16x2 (lo = a, hi = b).
__device__ __forceinline__ uint32_t pack_f16x2(float a, float b) {
    uint32_t r;
    asm("cvt.rn.f16x2.f32 %0, %1, %2;" : "=r"(r) : "f"(b), "f"(a));
    return r;
}
__device__ __forceinline__ float4 ldg_cs_f4(const float4* p) {
    float4 v;
    asm volatile("ld.global.cs.v4.f32 {%0, %1, %2, %3}, [%4];"
                 : "=f"(v.x), "=f"(v.y), "=f"(v.z), "=f"(v.w) : "l"(p));
    return v;
}

// Fused prep: x -> fp16 pre-swizzled (16B store per thread; x read with
// streaming hint so g_xh stays L2-resident for main) + W-pack + bias.
// W columns PERMUTED (round 14): each thread's 4 acc columns are 4
// consecutive logical j:  j = grp*64 + (jf>>1)*16 + 4*(n>>1) + 2*(jf&1) + (n&1)
__global__ void prep_all_kernel(const float* __restrict__ x,
                                const float* __restrict__ W_ih,
                                const float* __restrict__ b_ih,
                                const float* __restrict__ b_hh) {
    int g = blockIdx.x * blockDim.x + threadIdx.x;   // one 16B out-chunk each
    {   // conv: 16B fp16 chunk = 2 f32 float4 reads
        int row = g >> 4, q = g & 15;
        const float4* src = (const float4*)x + ((size_t)row << 5) + q * 2;
        float4 v0 = ldg_cs_f4(src);
        float4 v1 = ldg_cs_f4(src + 1);
        uint4 hv;
        hv.x = pack_f16x2(v0.x, v0.y);
        hv.y = pack_f16x2(v0.z, v0.w);
        hv.z = pack_f16x2(v1.x, v1.y);
        hv.w = pack_f16x2(v1.z, v1.w);
        char* dst = (char*)g_xh + (size_t)row * 256 + ((q ^ (row & 7)) << 4);
        *(uint4*)dst = hv;
    }
    if (g < NGRP * 192) {
        int grp = g / 192, r = g % 192;
        int gate = r / 64, jl = r % 64;
        int src = (gate == 0 ? 0 : (gate == 1 ? 512 : 768)) + grp * 64 + jl;
        g_bias[g] = b_ih[src] + b_hh[src];
    }
    if (g < NPACK * KDIM) {
        // fp16 B-frag coords: [grp][jfrag 8][gate 3][ks 8][lane 32][4 halves]
        int grp = g / 24576;          int r1 = g % 24576;
        int jf  = r1 / 3072;          int r2 = r1 % 3072;
        int gate = r2 / 1024;         int r3 = r2 % 1024;
        int ks  = r3 / 128;           int r4 = r3 % 128;
        int lane = r4 >> 2;           int rr = r4 & 3;
        int pair = rr >> 1;           int half = rr & 1;
        int gid = lane >> 2, tig = lane & 3;
        int k = ks * 16 + pair * 8 + 2 * tig + half;
        int j_global = grp * 64 + (jf >> 1) * 16 + ((gid >> 1) << 2)
                     + (jf & 1) * 2 + (gid & 1);
        int src_row = (gate == 0 ? 0 : (gate == 1 ? 512 : 768)) + j_global;
        g_Wp[g] = __float2half_rn(W_ih[src_row * KDIM + k]);
    }
}

// ---------------- helpers ----------------
__device__ __forceinline__ uint32_t smem_u32(const void* p) {
    uint32_t a;
    asm("{ .reg .u64 t; cvta.to.shared.u64 t, %1; cvt.u32.u64 %0, t; }" : "=r"(a) : "l"(p));
    return a;
}
__device__ __forceinline__ void cp_async16(uint32_t dst, const void* src) {
    asm volatile("cp.async.cg.shared.global [%0], [%1], 16;" :: "r"(dst), "l"(src));
}
__device__ __forceinline__ void cp_async_wait_all() {
    asm volatile("cp.async.commit_group;\ncp.async.wait_group 0;" ::: "memory");
}
__device__ __forceinline__ void mma_f16(float (&dacc)[4], const uint32_t (&a)[4],
                                        const uint32_t (&b)[2]) {
    asm volatile(
        "mma.sync.aligned.m16n8k16.row.col.f32.f16.f16.f32 "
        "{%0,%1,%2,%3}, {%4,%5,%6,%7}, {%8,%9}, {%0,%1,%2,%3};"
        : "+f"(dacc[0]), "+f"(dacc[1]), "+f"(dacc[2]), "+f"(dacc[3])
        : "r"(a[0]), "r"(a[1]), "r"(a[2]), "r"(a[3]), "r"(b[0]), "r"(b[1]));
}
__device__ __forceinline__ void ldsm_x4(uint32_t (&a)[4], uint32_t addr) {
    asm volatile("ldmatrix.sync.aligned.m8n8.x4.shared.b16 {%0,%1,%2,%3}, [%4];"
                 : "=r"(a[0]), "=r"(a[1]), "=r"(a[2]), "=r"(a[3]) : "r"(addr));
}
__device__ __forceinline__ float tanh_ap(float x) {
    float y;
    asm("tanh.approx.f32 %0, %1;" : "=f"(y) : "f"(x));
    return y;
}
__device__ __forceinline__ float sig_ap(float x) {
    return fmaf(0.5f, tanh_ap(0.5f * x), 0.5f);
}
// Streaming store (evict-first): keep g_xh resident in L2.
__device__ __forceinline__ void stg_cs_f4(float* p, float4 v) {
    asm volatile("st.global.cs.v4.f32 [%0], {%1, %2, %3, %4};"
                 :: "l"(p), "f"(v.x), "f"(v.y), "f"(v.z), "f"(v.w));
}

__global__ __launch_bounds__(NTHREADS, 2)
void lstm_mma_kernel(float* __restrict__ out) {
    extern __shared__ char smc[];
    float* bias_s = (float*)(smc + BIAS_OFF);
    char* Bs = smc + B_OFF;
    const uint32_t sb = smem_u32(smc);

    const int tid = threadIdx.x;
    const int lane = tid & 31;
    const int wid = tid >> 5;
    const int gid = lane >> 2;
    const int tig = lane & 3;
    const int wm = wid & 1;        // 2 m-warps * 64 rows
    const int wj = wid >> 1;       // 4 j-warps * (2 jf * 3 gates = 48 cols)
    // m-major: 4 grp-siblings of one m-tile adjacent -> share A via L2.
    const int grp = blockIdx.x & 3;
    const int bm = (blockIdx.x >> 2) * BM;

    // B fragments + A tile (both pre-packed fp16) via cp.async: zero regs,
    // zero conversion, 640 wf total.
    {
        const char* Bg = (const char*)g_Wp + (size_t)grp * B_BYTES;
#pragma unroll
        for (int i = 0; i < 12; ++i) {
            int c = i * NTHREADS + tid;
            cp_async16(sb + B_OFF + c * 16, Bg + c * 16);
        }
        const char* Ag = (const char*)g_xh + (size_t)bm * 256;
#pragma unroll
        for (int i = 0; i < 8; ++i) {
            int c = i * NTHREADS + tid;
            cp_async16(sb + A_OFF + c * 16, Ag + c * 16);
        }
    }
    if (tid < 192) bias_s[tid] = g_bias[grp * 192 + tid];
    cp_async_wait_all();
    __syncthreads();

    const int rb0 = wm * 64;
    const int lrow0 = rb0 + (lane & 7) + ((lane >> 3) & 1) * 8;
    const int lhi = lane >> 4;
    const uint32_t Au = sb + A_OFF;
    const char* Bw = Bs + (size_t)(wj * 2) * 3 * 8 * 256 + lane * 8;

    float acc[4][2][3][4];
#pragma unroll
    for (int mf = 0; mf < 4; ++mf)
#pragma unroll
        for (int jf = 0; jf < 2; ++jf)
#pragma unroll
            for (int g = 0; g < 3; ++g)
#pragma unroll
                for (int q = 0; q < 4; ++q) acc[mf][jf][g][q] = 0.0f;

    // Software pipeline: stage ks+1 loads while issuing ks MMAs.
    uint32_t a_cur[4][4], a_nxt[4][4];
    uint2 b_cur[2][3], b_nxt[2][3];
#pragma unroll
    for (int mf = 0; mf < 4; ++mf) {
        const int row = lrow0 + mf * 16;
        ldsm_x4(a_cur[mf], Au + row * 256 + ((lhi ^ (row & 7)) << 4));
    }
#pragma unroll
    for (int jf = 0; jf < 2; ++jf)
#pragma unroll
        for (int g = 0; g < 3; ++g)
            b_cur[jf][g] = *(const uint2*)(Bw + ((jf * 3 + g) * 8) * 256);

#pragma unroll
    for (int ks = 0; ks < 8; ++ks) {
        if (ks < 7) {
#pragma unroll
            for (int mf = 0; mf < 4; ++mf) {
                const int row = lrow0 + mf * 16;
                ldsm_x4(a_nxt[mf],
                        Au + row * 256 + ((((ks + 1) * 2 + lhi) ^ (row & 7)) << 4));
            }
#pragma unroll
            for (int jf = 0; jf < 2; ++jf)
#pragma unroll
                for (int g = 0; g < 3; ++g)
                    b_nxt[jf][g] = *(const uint2*)
                        (Bw + (((jf * 3 + g) * 8) + ks + 1) * 256);
        }
#pragma unroll
        for (int jf = 0; jf < 2; ++jf)
#pragma unroll
            for (int g = 0; g < 3; ++g) {
                uint32_t b[2] = { b_cur[jf][g].x, b_cur[jf][g].y };
#pragma unroll
                for (int mf = 0; mf < 4; ++mf)
                    mma_f16(acc[mf][jf][g], a_cur[mf], b);
            }
#pragma unroll
        for (int mf = 0; mf < 4; ++mf)
#pragma unroll
            for (int q = 0; q < 4; ++q) a_cur[mf][q] = a_nxt[mf][q];
#pragma unroll
        for (int jf = 0; jf < 2; ++jf)
#pragma unroll
            for (int g = 0; g < 3; ++g) b_cur[jf][g] = b_nxt[jf][g];
    }

    // Epilogue: B permutation -> this thread's 4 acc columns are logical
    // j = jl4..jl4+3 -> float4 coalesced stores.
    const int jl4 = wj * 16 + 4 * tig;
    const float4 bi = *(const float4*)(bias_s + jl4);
    const float4 bg = *(const float4*)(bias_s + 64 + jl4);
    const float4 bo = *(const float4*)(bias_s + 128 + jl4);
    const int jcol = grp * 64 + jl4;
#pragma unroll
    for (int mf = 0; mf < 4; ++mf) {
        const int m0 = bm + rb0 + mf * 16 + gid;
#pragma unroll
        for (int rr = 0; rr < 2; ++rr) {
            float4 hv, cv;
#pragma unroll
            for (int t = 0; t < 4; ++t) {
                const int jfl = t >> 1, co = t & 1;
                float iv = sig_ap(acc[mf][jfl][0][rr * 2 + co] + ((const float*)&bi)[t]);
                float gv = tanh_ap(acc[mf][jfl][1][rr * 2 + co] + ((const float*)&bg)[t]);
                float ov = sig_ap(acc[mf][jfl][2][rr * 2 + co] + ((const float*)&bo)[t]);
                float cc = iv * gv;
                float hh = ov * tanh_ap(cc);
                ((float*)&hv)[t] = hh;
                ((float*)&cv)[t] = cc;
            }
            size_t off = (size_t)(m0 + rr * 8) * HID + jcol;
            stg_cs_f4(out + off, hv);
            stg_cs_f4(out + (size_t)M_TOTAL * HID + off, cv);
        }
    }
}

extern "C" void kernel_launch(void* const* d_in, const int* in_sizes, int n_in,
                              void* d_out, int out_size) {
    const float* x    = (const float*)d_in[0];
    const float* W_ih = (const float*)d_in[1];
    // d_in[2] = W_hh unused (h_prev == 0 in reference)
    const float* b_ih = (const float*)d_in[3];
    const float* b_hh = (const float*)d_in[4];
    float* out = (float*)d_out;

    cudaFuncSetAttribute(lstm_mma_kernel,
                         cudaFuncAttributeMaxDynamicSharedMemorySize, SMEM_BYTES);

    // one 16B fp16 chunk per thread: M_TOTAL*KDIM*2/16 = 2M threads
    prep_all_kernel<<<(M_TOTAL * KDIM / 8) / 512, 512>>>(x, W_ih, b_ih, b_hh);
    lstm_mma_kernel<<<NGRP * MTILES, NTHREADS, SMEM_BYTES>>>(out);
}